// round 1
// baseline (speedup 1.0000x reference)
#include <cuda_runtime.h>
#include <math.h>

// ---------------------------------------------------------------------------
// Model constants
// ---------------------------------------------------------------------------
#define BATCH   2
#define SEQ     1024
#define NROWS   (BATCH * SEQ)      // 2048
#define DMODEL  1024
#define NHEAD   16
#define HDIM    64
#define TDIM    1024               // NHEAD * HDIM
#define FFDIM   4096
#define NLAYER  8
#define VOCAB   32000

// ---------------------------------------------------------------------------
// Device scratch (allocation-free)
// ---------------------------------------------------------------------------
__device__ float g_x   [NROWS * DMODEL];   // residual stream
__device__ float g_xn  [NROWS * DMODEL];   // layernormed
__device__ float g_u   [NROWS * 3 * TDIM]; // qkv
__device__ float g_attn[NROWS * TDIM];     // attention out (pre-Wo)
__device__ float g_h   [NROWS * FFDIM];    // ffn hidden

// ---------------------------------------------------------------------------
// GEMM: C[M,N] = A[M,K] @ B[N,K]^T   (+ epilogue)
// MODE 0: plain    MODE 1: gelu(acc + bias)    MODE 2: resid + acc (+ bias)
// Requires M%128==0, N%128==0, K%16==0 (true for all shapes here).
// ---------------------------------------------------------------------------
__device__ __forceinline__ float gelu_exact(float v) {
    return 0.5f * v * (1.0f + erff(v * 0.70710678118654752440f));
}

template<int MODE>
__global__ __launch_bounds__(256)
void gemm_tn(const float* __restrict__ A, const float* __restrict__ B,
             const float* __restrict__ bias, const float* __restrict__ resid,
             float* __restrict__ C, int M, int N, int K)
{
    constexpr int BK = 16;
    __shared__ float As[BK][128 + 4];
    __shared__ float Bs[BK][128 + 4];

    const int bm = blockIdx.y * 128;
    const int bn = blockIdx.x * 128;
    const int tid = threadIdx.x;
    const int tx = tid & 15;        // 0..15
    const int ty = tid >> 4;        // 0..15
    const int lr = tid >> 2;        // 0..63  (loader row)
    const int lk = (tid & 3) << 2;  // 0,4,8,12 (loader k, float4)

    float acc[8][8];
#pragma unroll
    for (int i = 0; i < 8; i++)
#pragma unroll
        for (int j = 0; j < 8; j++) acc[i][j] = 0.0f;

    const float* Aptr = A + (size_t)(bm + lr) * K + lk;
    const float* Bptr = B + (size_t)(bn + lr) * K + lk;
    const size_t rowskip = (size_t)64 * K;

    for (int k0 = 0; k0 < K; k0 += BK) {
        float4 a0 = *(const float4*)(Aptr + k0);
        float4 a1 = *(const float4*)(Aptr + rowskip + k0);
        float4 b0 = *(const float4*)(Bptr + k0);
        float4 b1 = *(const float4*)(Bptr + rowskip + k0);

        As[lk + 0][lr] = a0.x; As[lk + 1][lr] = a0.y;
        As[lk + 2][lr] = a0.z; As[lk + 3][lr] = a0.w;
        As[lk + 0][lr + 64] = a1.x; As[lk + 1][lr + 64] = a1.y;
        As[lk + 2][lr + 64] = a1.z; As[lk + 3][lr + 64] = a1.w;
        Bs[lk + 0][lr] = b0.x; Bs[lk + 1][lr] = b0.y;
        Bs[lk + 2][lr] = b0.z; Bs[lk + 3][lr] = b0.w;
        Bs[lk + 0][lr + 64] = b1.x; Bs[lk + 1][lr + 64] = b1.y;
        Bs[lk + 2][lr + 64] = b1.z; Bs[lk + 3][lr + 64] = b1.w;
        __syncthreads();

#pragma unroll
        for (int k = 0; k < BK; k++) {
            float4 a0v = *(const float4*)&As[k][ty * 4];
            float4 a1v = *(const float4*)&As[k][64 + ty * 4];
            float4 b0v = *(const float4*)&Bs[k][tx * 4];
            float4 b1v = *(const float4*)&Bs[k][64 + tx * 4];
            float ar[8] = {a0v.x, a0v.y, a0v.z, a0v.w, a1v.x, a1v.y, a1v.z, a1v.w};
            float br[8] = {b0v.x, b0v.y, b0v.z, b0v.w, b1v.x, b1v.y, b1v.z, b1v.w};
#pragma unroll
            for (int i = 0; i < 8; i++)
#pragma unroll
                for (int j = 0; j < 8; j++)
                    acc[i][j] = fmaf(ar[i], br[j], acc[i][j]);
        }
        __syncthreads();
    }

    // epilogue: 8 rows x 2 float4 cols per thread
#pragma unroll
    for (int i = 0; i < 8; i++) {
        const int r = bm + ((i < 4) ? (ty * 4 + i) : (64 + ty * 4 + (i - 4)));
#pragma unroll
        for (int cj = 0; cj < 2; cj++) {
            const int c = bn + cj * 64 + tx * 4;
            float4 v;
            v.x = acc[i][cj * 4 + 0]; v.y = acc[i][cj * 4 + 1];
            v.z = acc[i][cj * 4 + 2]; v.w = acc[i][cj * 4 + 3];
            if (MODE == 1) {
                float4 bb = *(const float4*)(bias + c);
                v.x = gelu_exact(v.x + bb.x); v.y = gelu_exact(v.y + bb.y);
                v.z = gelu_exact(v.z + bb.z); v.w = gelu_exact(v.w + bb.w);
            } else if (MODE == 2) {
                if (bias) {
                    float4 bb = *(const float4*)(bias + c);
                    v.x += bb.x; v.y += bb.y; v.z += bb.z; v.w += bb.w;
                }
                float4 rr = *(const float4*)(resid + (size_t)r * N + c);
                v.x += rr.x; v.y += rr.y; v.z += rr.z; v.w += rr.w;
            }
            *(float4*)(C + (size_t)r * N + c) = v;
        }
    }
}

// ---------------------------------------------------------------------------
// Embedding gather: x[row,:] = emb[ids[row],:]
// ---------------------------------------------------------------------------
__global__ void embed_kernel(const int* __restrict__ ids,
                             const float* __restrict__ emb,
                             float* __restrict__ x)
{
    const int row = blockIdx.x;
    const int id = ids[row];
    const float4* src = (const float4*)(emb + (size_t)id * DMODEL);
    float4* dst = (float4*)(x + (size_t)row * DMODEL);
    dst[threadIdx.x] = src[threadIdx.x];   // 256 threads * float4 = 1024
}

// ---------------------------------------------------------------------------
// LayerNorm: one 256-thread block per 1024-wide row
// ---------------------------------------------------------------------------
__global__ __launch_bounds__(256)
void layernorm_kernel(const float* __restrict__ x, const float* __restrict__ w,
                      const float* __restrict__ b, float* __restrict__ y)
{
    const int row = blockIdx.x;
    const int tid = threadIdx.x;
    __shared__ float red[256];

    float4 v = ((const float4*)(x + (size_t)row * DMODEL))[tid];
    float s = v.x + v.y + v.z + v.w;
    red[tid] = s; __syncthreads();
    for (int k = 128; k > 0; k >>= 1) {
        if (tid < k) red[tid] += red[tid + k];
        __syncthreads();
    }
    const float mu = red[0] * (1.0f / DMODEL);
    __syncthreads();

    float dx = v.x - mu, dy = v.y - mu, dz = v.z - mu, dw = v.w - mu;
    s = dx * dx + dy * dy + dz * dz + dw * dw;
    red[tid] = s; __syncthreads();
    for (int k = 128; k > 0; k >>= 1) {
        if (tid < k) red[tid] += red[tid + k];
        __syncthreads();
    }
    const float rstd = rsqrtf(red[0] * (1.0f / DMODEL) + 1e-5f);

    float4 wv = ((const float4*)w)[tid];
    float4 bv = ((const float4*)b)[tid];
    float4 o;
    o.x = dx * rstd * wv.x + bv.x;
    o.y = dy * rstd * wv.y + bv.y;
    o.z = dz * rstd * wv.z + bv.z;
    o.w = dw * rstd * wv.w + bv.w;
    ((float4*)(y + (size_t)row * DMODEL))[tid] = o;
}

// ---------------------------------------------------------------------------
// RoPE in-place on q,k halves of u. One thread per (row, pair).
// pairs per row: 2 regions (q,k) * 16 heads * 32 = 1024
// ---------------------------------------------------------------------------
__global__ __launch_bounds__(256)
void rope_kernel(float* __restrict__ u)
{
    const int idx = blockIdx.x * 256 + threadIdx.x;
    const int row = idx >> 10;
    const int j = idx & 1023;
    const int s = row & (SEQ - 1);
    const int which = j >> 9;        // 0 = q, 1 = k
    const int p = j & 511;
    const int head = p >> 5;
    const int i = p & 31;

    // inv_freq = 10000^(-2i/64)  = exp2(-(2i/64) * log2(10000))
    const float inv = exp2f(-(float)(2 * i) * (1.0f / 64.0f) * 13.287712379549449f);
    const float ang = (float)s * inv;
    float sn, cs;
    sincosf(ang, &sn, &cs);

    const size_t off = (size_t)row * (3 * TDIM) + (size_t)which * TDIM + head * HDIM + i;
    const float v0 = u[off];
    const float v1 = u[off + 32];
    u[off]      = v0 * cs - v1 * sn;
    u[off + 32] = v1 * cs + v0 * sn;
}

// ---------------------------------------------------------------------------
// Attention: one 128-thread block per (query, head, batch).
// scores kept in smem (S=1024 fits), two-pass softmax, causal.
// ---------------------------------------------------------------------------
__global__ __launch_bounds__(128)
void attn_kernel(const float* __restrict__ u, float* __restrict__ out)
{
    const int qi = blockIdx.x;
    const int h  = blockIdx.y;
    const int b  = blockIdx.z;
    const int tid = threadIdx.x;

    __shared__ float sq[HDIM];
    __shared__ float sc[SEQ];
    __shared__ float red[128];

    const size_t rowbase = (size_t)(b * SEQ) * (3 * TDIM);
    if (tid < HDIM)
        sq[tid] = u[rowbase + (size_t)qi * (3 * TDIM) + h * HDIM + tid];
    __syncthreads();

    const int nk = qi + 1;
    float lmax = -1e30f;
    for (int ki = tid; ki < nk; ki += 128) {
        const float* kp = u + rowbase + (size_t)ki * (3 * TDIM) + TDIM + h * HDIM;
        float d = 0.0f;
#pragma unroll
        for (int j = 0; j < HDIM; j++) d = fmaf(sq[j], kp[j], d);
        d *= 0.125f;                 // 1/sqrt(64)
        sc[ki] = d;
        lmax = fmaxf(lmax, d);
    }
    red[tid] = lmax; __syncthreads();
    for (int k = 64; k > 0; k >>= 1) {
        if (tid < k) red[tid] = fmaxf(red[tid], red[tid + k]);
        __syncthreads();
    }
    const float m = red[0];
    __syncthreads();

    float lsum = 0.0f;
    for (int ki = tid; ki < nk; ki += 128) {
        const float e = expf(sc[ki] - m);
        sc[ki] = e;
        lsum += e;
    }
    red[tid] = lsum; __syncthreads();
    for (int k = 64; k > 0; k >>= 1) {
        if (tid < k) red[tid] += red[tid + k];
        __syncthreads();
    }
    const float inv = 1.0f / red[0];
    __syncthreads();

    if (tid < HDIM) {
        const float* vp = u + rowbase + 2 * TDIM + h * HDIM + tid;
        float a0 = 0.0f, a1 = 0.0f, a2 = 0.0f, a3 = 0.0f;
        int ki = 0;
        for (; ki + 4 <= nk; ki += 4) {
            a0 = fmaf(sc[ki + 0], vp[(size_t)(ki + 0) * (3 * TDIM)], a0);
            a1 = fmaf(sc[ki + 1], vp[(size_t)(ki + 1) * (3 * TDIM)], a1);
            a2 = fmaf(sc[ki + 2], vp[(size_t)(ki + 2) * (3 * TDIM)], a2);
            a3 = fmaf(sc[ki + 3], vp[(size_t)(ki + 3) * (3 * TDIM)], a3);
        }
        for (; ki < nk; ki++)
            a0 = fmaf(sc[ki], vp[(size_t)ki * (3 * TDIM)], a0);
        out[(size_t)(b * SEQ + qi) * TDIM + h * HDIM + tid] =
            (a0 + a1 + a2 + a3) * inv;
    }
}

// ---------------------------------------------------------------------------
// Host orchestration
// ---------------------------------------------------------------------------
extern "C" void kernel_launch(void* const* d_in, const int* in_sizes, int n_in,
                              void* d_out, int out_size)
{
    (void)in_sizes; (void)n_in; (void)out_size;

    const int*   ids = (const int*)  d_in[0];
    const float* emb = (const float*)d_in[1];
    const float* Wu  = (const float*)d_in[2];
    const float* Wo  = (const float*)d_in[3];
    const float* n1w = (const float*)d_in[4];
    const float* n1b = (const float*)d_in[5];
    const float* n2w = (const float*)d_in[6];
    const float* n2b = (const float*)d_in[7];
    const float* f1w = (const float*)d_in[8];
    const float* f1b = (const float*)d_in[9];
    const float* f2w = (const float*)d_in[10];
    const float* f2b = (const float*)d_in[11];
    const float* fnw = (const float*)d_in[12];
    const float* fnb = (const float*)d_in[13];
    float* out = (float*)d_out;

    float *x, *xn, *u, *attn, *hbuf;
    cudaGetSymbolAddress((void**)&x,    g_x);
    cudaGetSymbolAddress((void**)&xn,   g_xn);
    cudaGetSymbolAddress((void**)&u,    g_u);
    cudaGetSymbolAddress((void**)&attn, g_attn);
    cudaGetSymbolAddress((void**)&hbuf, g_h);

    embed_kernel<<<NROWS, 256>>>(ids, emb, x);

    for (int l = 0; l < NLAYER; l++) {
        const float* Wu_l  = Wu  + (size_t)l * 3 * TDIM * DMODEL;
        const float* Wo_l  = Wo  + (size_t)l * DMODEL * TDIM;
        const float* f1w_l = f1w + (size_t)l * FFDIM * DMODEL;
        const float* f1b_l = f1b + (size_t)l * FFDIM;
        const float* f2w_l = f2w + (size_t)l * DMODEL * FFDIM;
        const float* f2b_l = f2b + (size_t)l * DMODEL;

        layernorm_kernel<<<NROWS, 256>>>(x, n1w + l * DMODEL, n1b + l * DMODEL, xn);

        gemm_tn<0><<<dim3(3 * TDIM / 128, NROWS / 128), 256>>>(
            xn, Wu_l, nullptr, nullptr, u, NROWS, 3 * TDIM, DMODEL);

        rope_kernel<<<(NROWS * 1024) / 256, 256>>>(u);

        attn_kernel<<<dim3(SEQ, NHEAD, BATCH), 128>>>(u, attn);

        gemm_tn<2><<<dim3(DMODEL / 128, NROWS / 128), 256>>>(
            attn, Wo_l, nullptr, x, x, NROWS, DMODEL, TDIM);

        layernorm_kernel<<<NROWS, 256>>>(x, n2w + l * DMODEL, n2b + l * DMODEL, xn);

        gemm_tn<1><<<dim3(FFDIM / 128, NROWS / 128), 256>>>(
            xn, f1w_l, f1b_l, nullptr, hbuf, NROWS, FFDIM, DMODEL);

        gemm_tn<2><<<dim3(DMODEL / 128, NROWS / 128), 256>>>(
            hbuf, f2w_l, f2b_l, x, x, NROWS, DMODEL, FFDIM);
    }

    layernorm_kernel<<<NROWS, 256>>>(x, fnw, fnb, xn);

    gemm_tn<0><<<dim3(VOCAB / 128, NROWS / 128), 256>>>(
        xn, emb, nullptr, nullptr, out, NROWS, VOCAB, DMODEL);
}

// round 2
// speedup vs baseline: 4.3695x; 4.3695x over previous
#include <cuda_runtime.h>
#include <math.h>

// ---------------------------------------------------------------------------
// Model constants
// ---------------------------------------------------------------------------
#define BATCH   2
#define SEQ     1024
#define NROWS   (BATCH * SEQ)      // 2048
#define DMODEL  1024
#define NHEAD   16
#define HDIM    64
#define TDIM    1024               // NHEAD * HDIM
#define FFDIM   4096
#define NLAYER  8
#define VOCAB   32000

// ---------------------------------------------------------------------------
// Device scratch (allocation-free)
// ---------------------------------------------------------------------------
__device__ float g_x   [NROWS * DMODEL];   // residual stream
__device__ float g_xn  [NROWS * DMODEL];   // layernormed
__device__ float g_u   [NROWS * 3 * TDIM]; // qkv
__device__ float g_attn[NROWS * TDIM];     // attention out (pre-Wo)
__device__ float g_h   [NROWS * FFDIM];    // ffn hidden

// ---------------------------------------------------------------------------
// Helpers
// ---------------------------------------------------------------------------
__device__ __forceinline__ float gelu_exact(float v) {
    return 0.5f * v * (1.0f + erff(v * 0.70710678118654752440f));
}

__device__ __forceinline__ unsigned f2tf32(float f) {
    unsigned u;
    asm("cvt.rna.tf32.f32 %0, %1;" : "=r"(u) : "f"(f));
    return u;
}

__device__ __forceinline__ void mma_tf32(float* c, const unsigned* a, const unsigned* b) {
    asm volatile(
        "mma.sync.aligned.m16n8k8.row.col.f32.tf32.tf32.f32 "
        "{%0,%1,%2,%3},{%4,%5,%6,%7},{%8,%9},{%0,%1,%2,%3};"
        : "+f"(c[0]), "+f"(c[1]), "+f"(c[2]), "+f"(c[3])
        : "r"(a[0]), "r"(a[1]), "r"(a[2]), "r"(a[3]), "r"(b[0]), "r"(b[1]));
}

// ---------------------------------------------------------------------------
// Tensor-core GEMM (tf32): C[M,N] = A[M,K] @ B[N,K]^T  (+ epilogue)
// MODE 0: plain    MODE 1: gelu(acc + bias)    MODE 2: resid + acc (+ bias)
// M%128==0, N%128==0, K%16==0.
// Block 256 thr = 8 warps; tile 128x128, BK=16, double-buffered smem.
// smem layout [k][m|n] padded to 136 -> fragment LDS bank = (8t+g)%32, CF.
// ---------------------------------------------------------------------------
template<int MODE>
__global__ __launch_bounds__(256)
void gemm_mma(const float* __restrict__ A, const float* __restrict__ B,
              const float* __restrict__ bias, const float* __restrict__ resid,
              float* __restrict__ C, int M, int N, int K)
{
    constexpr int BK = 16;
    constexpr int LD = 136;
    __shared__ unsigned As[2][BK][LD];
    __shared__ unsigned Bs[2][BK][LD];

    const int bm = blockIdx.y * 128;
    const int bn = blockIdx.x * 128;
    const int tid  = threadIdx.x;
    const int warp = tid >> 5;
    const int lane = tid & 31;
    const int g = lane >> 2;       // group id 0..7
    const int t = lane & 3;        // thread-in-group 0..3
    const int moff = (warp & 3) * 32;
    const int noff = (warp >> 2) * 64;

    // global loader coords: 128 rows x 16 cols, 256 threads x 2 float4
    const int ldRow = tid >> 2;            // 0..63 (+64 for j=1)
    const int ldCol = (tid & 3) * 4;       // 0,4,8,12
    const float* Ag = A + (size_t)(bm + ldRow) * K + ldCol;
    const float* Bg = B + (size_t)(bn + ldRow) * K + ldCol;
    const size_t rowskip = (size_t)64 * K;

    float acc[2][8][4];
#pragma unroll
    for (int mi = 0; mi < 2; mi++)
#pragma unroll
        for (int ni = 0; ni < 8; ni++)
#pragma unroll
            for (int e = 0; e < 4; e++) acc[mi][ni][e] = 0.0f;

    float4 av0, av1, bv0, bv1;

    // prologue: load+store tile 0
    av0 = *(const float4*)(Ag);
    av1 = *(const float4*)(Ag + rowskip);
    bv0 = *(const float4*)(Bg);
    bv1 = *(const float4*)(Bg + rowskip);
#pragma unroll
    for (int e = 0; e < 4; e++) {
        As[0][ldCol + e][ldRow]      = f2tf32(((const float*)&av0)[e]);
        As[0][ldCol + e][ldRow + 64] = f2tf32(((const float*)&av1)[e]);
        Bs[0][ldCol + e][ldRow]      = f2tf32(((const float*)&bv0)[e]);
        Bs[0][ldCol + e][ldRow + 64] = f2tf32(((const float*)&bv1)[e]);
    }
    __syncthreads();

    int p = 0;
    for (int k0 = 0; k0 < K; k0 += BK) {
        const bool has_next = (k0 + BK) < K;
        if (has_next) {
            av0 = *(const float4*)(Ag + k0 + BK);
            av1 = *(const float4*)(Ag + rowskip + k0 + BK);
            bv0 = *(const float4*)(Bg + k0 + BK);
            bv1 = *(const float4*)(Bg + rowskip + k0 + BK);
        }

#pragma unroll
        for (int kk = 0; kk < BK; kk += 8) {
            unsigned afr[2][4];
#pragma unroll
            for (int mi = 0; mi < 2; mi++) {
                const int m = moff + 16 * mi + g;
                afr[mi][0] = As[p][kk + t][m];
                afr[mi][1] = As[p][kk + t][m + 8];
                afr[mi][2] = As[p][kk + t + 4][m];
                afr[mi][3] = As[p][kk + t + 4][m + 8];
            }
            unsigned bfr[8][2];
#pragma unroll
            for (int ni = 0; ni < 8; ni++) {
                const int n = noff + 8 * ni + g;
                bfr[ni][0] = Bs[p][kk + t][n];
                bfr[ni][1] = Bs[p][kk + t + 4][n];
            }
#pragma unroll
            for (int mi = 0; mi < 2; mi++)
#pragma unroll
                for (int ni = 0; ni < 8; ni++)
                    mma_tf32(acc[mi][ni], afr[mi], bfr[ni]);
        }

        if (has_next) {
            const int q = 1 - p;
#pragma unroll
            for (int e = 0; e < 4; e++) {
                As[q][ldCol + e][ldRow]      = f2tf32(((const float*)&av0)[e]);
                As[q][ldCol + e][ldRow + 64] = f2tf32(((const float*)&av1)[e]);
                Bs[q][ldCol + e][ldRow]      = f2tf32(((const float*)&bv0)[e]);
                Bs[q][ldCol + e][ldRow + 64] = f2tf32(((const float*)&bv1)[e]);
            }
        }
        __syncthreads();
        p ^= 1;
    }

    // epilogue: per atom, rows (r0, r0+8), cols (c, c+1)
#pragma unroll
    for (int mi = 0; mi < 2; mi++) {
        const int r0 = bm + moff + 16 * mi + g;
#pragma unroll
        for (int ni = 0; ni < 8; ni++) {
            const int c = bn + noff + 8 * ni + 2 * t;
            float v00 = acc[mi][ni][0], v01 = acc[mi][ni][1];
            float v10 = acc[mi][ni][2], v11 = acc[mi][ni][3];
            if (MODE == 1) {
                const float b0 = bias[c], b1 = bias[c + 1];
                v00 = gelu_exact(v00 + b0); v01 = gelu_exact(v01 + b1);
                v10 = gelu_exact(v10 + b0); v11 = gelu_exact(v11 + b1);
            } else if (MODE == 2) {
                if (bias) {
                    const float b0 = bias[c], b1 = bias[c + 1];
                    v00 += b0; v01 += b1; v10 += b0; v11 += b1;
                }
                const float2 rr0 = *(const float2*)(resid + (size_t)r0 * N + c);
                const float2 rr1 = *(const float2*)(resid + (size_t)(r0 + 8) * N + c);
                v00 += rr0.x; v01 += rr0.y; v10 += rr1.x; v11 += rr1.y;
            }
            float2 o0; o0.x = v00; o0.y = v01;
            float2 o1; o1.x = v10; o1.y = v11;
            *(float2*)(C + (size_t)r0 * N + c) = o0;
            *(float2*)(C + (size_t)(r0 + 8) * N + c) = o1;
        }
    }
}

// ---------------------------------------------------------------------------
// Embedding gather
// ---------------------------------------------------------------------------
__global__ void embed_kernel(const int* __restrict__ ids,
                             const float* __restrict__ emb,
                             float* __restrict__ x)
{
    const int row = blockIdx.x;
    const int id = ids[row];
    const float4* src = (const float4*)(emb + (size_t)id * DMODEL);
    float4* dst = (float4*)(x + (size_t)row * DMODEL);
    dst[threadIdx.x] = src[threadIdx.x];
}

// ---------------------------------------------------------------------------
// LayerNorm
// ---------------------------------------------------------------------------
__global__ __launch_bounds__(256)
void layernorm_kernel(const float* __restrict__ x, const float* __restrict__ w,
                      const float* __restrict__ b, float* __restrict__ y)
{
    const int row = blockIdx.x;
    const int tid = threadIdx.x;
    __shared__ float red[256];

    float4 v = ((const float4*)(x + (size_t)row * DMODEL))[tid];
    float s = v.x + v.y + v.z + v.w;
    red[tid] = s; __syncthreads();
    for (int k = 128; k > 0; k >>= 1) {
        if (tid < k) red[tid] += red[tid + k];
        __syncthreads();
    }
    const float mu = red[0] * (1.0f / DMODEL);
    __syncthreads();

    float dx = v.x - mu, dy = v.y - mu, dz = v.z - mu, dw = v.w - mu;
    s = dx * dx + dy * dy + dz * dz + dw * dw;
    red[tid] = s; __syncthreads();
    for (int k = 128; k > 0; k >>= 1) {
        if (tid < k) red[tid] += red[tid + k];
        __syncthreads();
    }
    const float rstd = rsqrtf(red[0] * (1.0f / DMODEL) + 1e-5f);

    float4 wv = ((const float4*)w)[tid];
    float4 bv = ((const float4*)b)[tid];
    float4 o;
    o.x = dx * rstd * wv.x + bv.x;
    o.y = dy * rstd * wv.y + bv.y;
    o.z = dz * rstd * wv.z + bv.z;
    o.w = dw * rstd * wv.w + bv.w;
    ((float4*)(y + (size_t)row * DMODEL))[tid] = o;
}

// ---------------------------------------------------------------------------
// RoPE in-place on q,k halves of u
// ---------------------------------------------------------------------------
__global__ __launch_bounds__(256)
void rope_kernel(float* __restrict__ u)
{
    const int idx = blockIdx.x * 256 + threadIdx.x;
    const int row = idx >> 10;
    const int j = idx & 1023;
    const int s = row & (SEQ - 1);
    const int which = j >> 9;        // 0 = q, 1 = k
    const int pp = j & 511;
    const int head = pp >> 5;
    const int i = pp & 31;

    const float inv = exp2f(-(float)(2 * i) * (1.0f / 64.0f) * 13.287712379549449f);
    const float ang = (float)s * inv;
    float sn, cs;
    sincosf(ang, &sn, &cs);

    const size_t off = (size_t)row * (3 * TDIM) + (size_t)which * TDIM + head * HDIM + i;
    const float v0 = u[off];
    const float v1 = u[off + 32];
    u[off]      = v0 * cs - v1 * sn;
    u[off + 32] = v1 * cs + v0 * sn;
}

// ---------------------------------------------------------------------------
// Attention v2: flash-style, 8 queries per block (warp per query),
// online softmax, K/V staged in smem 64-row chunks (8x reuse).
// grid = (SEQ/8, NHEAD, BATCH), 256 threads.
// ---------------------------------------------------------------------------
#define QT 8
__global__ __launch_bounds__(256)
void attn_kernel(const float* __restrict__ u, float* __restrict__ out)
{
    const int q0 = blockIdx.x * QT;
    const int h  = blockIdx.y;
    const int b  = blockIdx.z;
    const int tid  = threadIdx.x;
    const int warp = tid >> 5;
    const int lane = tid & 31;
    const int q = q0 + warp;

    __shared__ float sq [QT][HDIM];      // 2 KB
    __shared__ float ksm[64][65];        // 16.25 KB + pad
    __shared__ float vsm[64][65];

    const size_t rowbase = (size_t)(b * SEQ) * (3 * TDIM);

    // load Q tile
    for (int i = tid; i < QT * HDIM; i += 256) {
        const int r = i >> 6, c = i & 63;
        sq[r][c] = u[rowbase + (size_t)(q0 + r) * (3 * TDIM) + h * HDIM + c];
    }
    __syncthreads();

    // hoist q row into registers (broadcast LDS once)
    float qreg[HDIM];
#pragma unroll
    for (int j = 0; j < HDIM; j++) qreg[j] = sq[warp][j];

    float m = -1e30f, l = 0.0f, a0 = 0.0f, a1 = 0.0f;
    const int nkmax = q0 + QT;

    for (int c0 = 0; c0 < nkmax; c0 += 64) {
        // load K and V chunks: 64 rows x 64 floats each
        for (int i4 = tid; i4 < 1024; i4 += 256) {
            const int r = i4 >> 4;
            const int c = (i4 & 15) * 4;
            const size_t base = rowbase + (size_t)(c0 + r) * (3 * TDIM) + h * HDIM + c;
            const float4 kv = *(const float4*)(u + base + TDIM);
            const float4 vv = *(const float4*)(u + base + 2 * TDIM);
            ksm[r][c + 0] = kv.x; ksm[r][c + 1] = kv.y;
            ksm[r][c + 2] = kv.z; ksm[r][c + 3] = kv.w;
            vsm[r][c + 0] = vv.x; vsm[r][c + 1] = vv.y;
            vsm[r][c + 2] = vv.z; vsm[r][c + 3] = vv.w;
        }
        __syncthreads();

        // scores for rows (c0+lane) and (c0+lane+32)
        float d0 = 0.0f, d1 = 0.0f;
#pragma unroll
        for (int j = 0; j < HDIM; j++) {
            d0 = fmaf(qreg[j], ksm[lane][j], d0);
            d1 = fmaf(qreg[j], ksm[lane + 32][j], d1);
        }
        d0 *= 0.125f; d1 *= 0.125f;
        const float s0 = (c0 + lane      <= q) ? d0 : -1e30f;
        const float s1 = (c0 + lane + 32 <= q) ? d1 : -1e30f;

        float cmax = fmaxf(s0, s1);
#pragma unroll
        for (int off = 16; off > 0; off >>= 1)
            cmax = fmaxf(cmax, __shfl_xor_sync(0xffffffff, cmax, off));

        const float mnew  = fmaxf(m, cmax);
        const float scale = __expf(m - mnew);
        const float p0 = __expf(s0 - mnew);
        const float p1 = __expf(s1 - mnew);
        l = l * scale + p0 + p1;
        a0 *= scale; a1 *= scale;

#pragma unroll 8
        for (int r = 0; r < 32; r++) {
            const float pr = __shfl_sync(0xffffffff, p0, r);
            a0 = fmaf(pr, vsm[r][lane], a0);
            a1 = fmaf(pr, vsm[r][lane + 32], a1);
        }
#pragma unroll 8
        for (int r = 0; r < 32; r++) {
            const float pr = __shfl_sync(0xffffffff, p1, r);
            a0 = fmaf(pr, vsm[r + 32][lane], a0);
            a1 = fmaf(pr, vsm[r + 32][lane + 32], a1);
        }
        m = mnew;
        __syncthreads();
    }

#pragma unroll
    for (int off = 16; off > 0; off >>= 1)
        l += __shfl_xor_sync(0xffffffff, l, off);
    const float inv = 1.0f / l;

    out[(size_t)(b * SEQ + q) * TDIM + h * HDIM + lane]      = a0 * inv;
    out[(size_t)(b * SEQ + q) * TDIM + h * HDIM + lane + 32] = a1 * inv;
}

// ---------------------------------------------------------------------------
// Host orchestration
// ---------------------------------------------------------------------------
extern "C" void kernel_launch(void* const* d_in, const int* in_sizes, int n_in,
                              void* d_out, int out_size)
{
    (void)in_sizes; (void)n_in; (void)out_size;

    const int*   ids = (const int*)  d_in[0];
    const float* emb = (const float*)d_in[1];
    const float* Wu  = (const float*)d_in[2];
    const float* Wo  = (const float*)d_in[3];
    const float* n1w = (const float*)d_in[4];
    const float* n1b = (const float*)d_in[5];
    const float* n2w = (const float*)d_in[6];
    const float* n2b = (const float*)d_in[7];
    const float* f1w = (const float*)d_in[8];
    const float* f1b = (const float*)d_in[9];
    const float* f2w = (const float*)d_in[10];
    const float* f2b = (const float*)d_in[11];
    const float* fnw = (const float*)d_in[12];
    const float* fnb = (const float*)d_in[13];
    float* out = (float*)d_out;

    float *x, *xn, *u, *attn, *hbuf;
    cudaGetSymbolAddress((void**)&x,    g_x);
    cudaGetSymbolAddress((void**)&xn,   g_xn);
    cudaGetSymbolAddress((void**)&u,    g_u);
    cudaGetSymbolAddress((void**)&attn, g_attn);
    cudaGetSymbolAddress((void**)&hbuf, g_h);

    embed_kernel<<<NROWS, 256>>>(ids, emb, x);

    for (int l = 0; l < NLAYER; l++) {
        const float* Wu_l  = Wu  + (size_t)l * 3 * TDIM * DMODEL;
        const float* Wo_l  = Wo  + (size_t)l * DMODEL * TDIM;
        const float* f1w_l = f1w + (size_t)l * FFDIM * DMODEL;
        const float* f1b_l = f1b + (size_t)l * FFDIM;
        const float* f2w_l = f2w + (size_t)l * DMODEL * FFDIM;
        const float* f2b_l = f2b + (size_t)l * DMODEL;

        layernorm_kernel<<<NROWS, 256>>>(x, n1w + l * DMODEL, n1b + l * DMODEL, xn);

        gemm_mma<0><<<dim3(3 * TDIM / 128, NROWS / 128), 256>>>(
            xn, Wu_l, nullptr, nullptr, u, NROWS, 3 * TDIM, DMODEL);

        rope_kernel<<<(NROWS * 1024) / 256, 256>>>(u);

        attn_kernel<<<dim3(SEQ / QT, NHEAD, BATCH), 256>>>(u, attn);

        gemm_mma<2><<<dim3(DMODEL / 128, NROWS / 128), 256>>>(
            attn, Wo_l, nullptr, x, x, NROWS, DMODEL, TDIM);

        layernorm_kernel<<<NROWS, 256>>>(x, n2w + l * DMODEL, n2b + l * DMODEL, xn);

        gemm_mma<1><<<dim3(FFDIM / 128, NROWS / 128), 256>>>(
            xn, f1w_l, f1b_l, nullptr, hbuf, NROWS, FFDIM, DMODEL);

        gemm_mma<2><<<dim3(DMODEL / 128, NROWS / 128), 256>>>(
            hbuf, f2w_l, f2b_l, x, x, NROWS, DMODEL, FFDIM);
    }

    layernorm_kernel<<<NROWS, 256>>>(x, fnw, fnb, xn);

    gemm_mma<0><<<dim3(VOCAB / 128, NROWS / 128), 256>>>(
        xn, emb, nullptr, nullptr, out, NROWS, VOCAB, DMODEL);
}